// round 6
// baseline (speedup 1.0000x reference)
#include <cuda_runtime.h>
#include <math.h>
#include <stdint.h>

#define NTOK   20
#define DVEC   256
#define KSAMP  4096
#define NSTEP  19
#define WPB    8                 /* warps (samples) per block */
#define NBLK   (KSAMP/WPB)       /* 512 blocks */
#define GPW    (NSTEP*NTOK)      /* 380 gumbel keys per sample */

__device__ float          g_S[NTOK*6];   // [i][0..2]=x_i.Wf+b, [i][3..5]=x_i.Wa
__device__ float          g_score[KSAMP];
__device__ unsigned char  g_legal[KSAMP];
__device__ int            g_prep_done   = 0;  // reset by last block each run
__device__ int            g_blocks_done = 0;  // reset by last block each run

// ---------------- Threefry-2x32 (20 rounds), identical to JAX ----------------
__host__ __device__ __forceinline__ void tf_block(uint32_t k0, uint32_t k1,
                                                  uint32_t x0, uint32_t x1,
                                                  uint32_t* o0, uint32_t* o1) {
  uint32_t ks2 = k0 ^ k1 ^ 0x1BD11BDAu;
  x0 += k0; x1 += k1;
#define TF_ROT(r) { x0 += x1; x1 = (x1 << (r)) | (x1 >> (32 - (r))); x1 ^= x0; }
  TF_ROT(13) TF_ROT(15) TF_ROT(26) TF_ROT(6)
  x0 += k1;  x1 += ks2 + 1u;
  TF_ROT(17) TF_ROT(29) TF_ROT(16) TF_ROT(24)
  x0 += ks2; x1 += k0 + 2u;
  TF_ROT(13) TF_ROT(15) TF_ROT(26) TF_ROT(6)
  x0 += k0;  x1 += k1 + 3u;
  TF_ROT(17) TF_ROT(29) TF_ROT(16) TF_ROT(24)
  x0 += k1;  x1 += ks2 + 4u;
  TF_ROT(13) TF_ROT(15) TF_ROT(26) TF_ROT(6)
  x0 += ks2; x1 += k0 + 5u;
#undef TF_ROT
  *o0 = x0; *o1 = x1;
}

__device__ __forceinline__ uint32_t tf_bits32(uint32_t k0, uint32_t k1, uint32_t i) {
  uint32_t a, b;
  tf_block(k0, k1, 0u, i, &a, &b);
  return a ^ b;
}

// ---------------- warp-per-token prep (lane owns 8 dims, shuffle-only) --------
__device__ __forceinline__ void prep_token(int i, int lane,
                                           const int* __restrict__ ids,
                                           const float* __restrict__ emb,
                                           const float* __restrict__ lv,
                                           const float* __restrict__ fx,
                                           const float* __restrict__ Wf,
                                           const float* __restrict__ Wa,
                                           const float* __restrict__ bop) {
  const unsigned FULL = 0xFFFFFFFFu;
  int id = ids[i];
  const float4* er = (const float4*)(emb + (size_t)id * DVEC);
  const float4* fr = (const float4*)(fx  + (size_t)id * DVEC);
  float4 e0 = er[lane * 2], e1 = er[lane * 2 + 1];
  float4 f0 = fr[lane * 2], f1 = fr[lane * 2 + 1];
  float lvv = lv[id];

  float ev[8] = {e0.x, e0.y, e0.z, e0.w, e1.x, e1.y, e1.z, e1.w};
  float fv[8] = {f0.x, f0.y, f0.z, f0.w, f1.x, f1.y, f1.z, f1.w};

  float m = ev[0];
#pragma unroll
  for (int j = 1; j < 8; j++) m = fmaxf(m, ev[j]);
#pragma unroll
  for (int o = 16; o; o >>= 1) m = fmaxf(m, __shfl_xor_sync(FULL, m, o));

  float ex[8]; float sm = 0.0f;
#pragma unroll
  for (int j = 0; j < 8; j++) { ex[j] = expf(ev[j] - m); sm += ex[j]; }
#pragma unroll
  for (int o = 16; o; o >>= 1) sm += __shfl_xor_sync(FULL, sm, o);

  float x[8];
#pragma unroll
  for (int j = 0; j < 8; j++) x[j] = (ex[j] / sm) * lvv + fv[j];

  float p[6] = {0, 0, 0, 0, 0, 0};
#pragma unroll
  for (int j = 0; j < 8; j++) {
    int d = lane * 8 + j;
    p[0] += x[j] * Wf[d * 3 + 0];
    p[1] += x[j] * Wf[d * 3 + 1];
    p[2] += x[j] * Wf[d * 3 + 2];
    p[3] += x[j] * Wa[d * 3 + 0];
    p[4] += x[j] * Wa[d * 3 + 1];
    p[5] += x[j] * Wa[d * 3 + 2];
  }
#pragma unroll
  for (int o = 16; o; o >>= 1) {
#pragma unroll
    for (int q = 0; q < 6; q++) p[q] += __shfl_xor_sync(FULL, p[q], o);
  }
  if (lane == 0) {
#pragma unroll
    for (int q = 0; q < 6; q++)
      g_S[i * 6 + q] = p[q] + (q < 3 ? bop[q] : 0.0f);
    __threadfence();
    atomicAdd(&g_prep_done, 1);
  }
}

// ---------------- single fused kernel, barrier-free hot path ------------------
__global__ __launch_bounds__(256) void fused_all(
    uint32_t kop0, uint32_t kop1, uint32_t kg0, uint32_t kg1,
    const int* __restrict__ ids, const float* __restrict__ emb,
    const float* __restrict__ lv, const float* __restrict__ fx,
    const float* __restrict__ Wf, const float* __restrict__ Wa,
    const float* __restrict__ bop, float* __restrict__ out) {
  __shared__ uint32_t skey[WPB][384];   // packed keys: ((bits>>9)+1)<<5 | (31-j)
  __shared__ float    sred[256];
  __shared__ int      scnt[256];

  const unsigned FULL = 0xFFFFFFFFu;
  int tid = threadIdx.x;
  int lane = tid & 31, w = tid >> 5;
  int k = blockIdx.x * WPB + w;          // sample 0..4095

  // blocks 0..19, warp 0: prep one token first (DRAM loads fly early)
  if (blockIdx.x < NTOK && w == 0)
    prep_token(blockIdx.x, lane, ids, emb, lv, fx, Wf, Wa, bop);

  // ops: lane t computes step t's op; pack into two ballot words
  uint32_t opbits = tf_bits32(kop0, kop1, (uint32_t)(lane * KSAMP + k));
  int my_op = (int)(((opbits >> 16) % 3u + (opbits & 0xFFFFu) % 3u) % 3u);
  uint32_t opb0 = __ballot_sync(FULL, my_op & 1);
  uint32_t opb1 = __ballot_sync(FULL, my_op & 2);

  // gumbel sort-keys: ordering of -log(-log(u)) == ordering of (bits>>9).
  // Pack lane for tie-break: equal key -> higher (31-j) -> lower slot wins,
  // exactly jax.lax.top_k semantics. Masked lanes use 0 (all keys > 0).
#pragma unroll
  for (int r = 0; r < 12; r++) {
    int l = lane + 32 * r;
    if (l < GPW) {
      int t = l / 20;
      int j = l - t * 20;
      uint32_t idx = (uint32_t)t * 81920u + (uint32_t)k * 20u + (uint32_t)j;
      uint32_t key = tf_bits32(kg0, kg1, idx) >> 9;
      skey[w][l] = ((key + 1u) << 5) | (31u - (uint32_t)j);
    }
  }
  __syncwarp();

  // per-warp wait for the 20 prep warps (no block barrier)
  if (lane == 0) {
    while (*((volatile int*)&g_prep_done) != NTOK) __nanosleep(40);
  }
  __syncwarp();
  __threadfence();                       // acquire g_S

  // lane j holds S[j][*] in registers
  float Sf0 = 0, Sf1 = 0, Sf2 = 0, Sa0 = 0, Sa1 = 0, Sa2 = 0;
  if (lane < NTOK) {
    const float* p = g_S + lane * 6;
    Sf0 = p[0]; Sf1 = p[1]; Sf2 = p[2];
    Sa0 = p[3]; Sa1 = p[4]; Sa2 = p[5];
  }

  unsigned avail = 0xFFFFFu;
  unsigned f1 = 0u, f2 = 0u;
  int myptr = lane;                      // slot`lane`'s dvec-row ptr
  float score = 0.0f;
  bool legal = true;

#pragma unroll
  for (int t = 0; t < NSTEP; t++) {
    int op = (int)(((opb0 >> t) & 1u) | (((opb1 >> t) & 1u) << 1));

    uint32_t s = (lane < NTOK && ((avail >> lane) & 1u)) ? skey[w][t * 20 + lane] : 0u;

    uint32_t m1 = __reduce_max_sync(FULL, s);
    int b1 = (int)((~m1) & 31u);                       // = 31 - (m1&31)
    uint32_t s2 = (lane == b1) ? 0u : s;
    uint32_t m2 = __reduce_max_sync(FULL, s2);
    int b2 = (int)((~m2) & 31u);

    avail &= ~(1u << b2);

    // score lookup: op-select own S, route via ptr of b1/b2 (off critical path)
    float vf = (op == 0) ? Sf0 : ((op == 1) ? Sf1 : Sf2);
    float va = (op == 0) ? Sa0 : ((op == 1) ? Sa1 : Sa2);
    int pf = __shfl_sync(FULL, myptr, b1);
    int pa = __shfl_sync(FULL, myptr, b2);
    score += __shfl_sync(FULL, vf, pf) + __shfl_sync(FULL, va, pa);

    unsigned of1 = (f1 >> b1) & 1u;
    unsigned of2 = (f2 >> b1) & 1u;
    bool bad = ((op != 2) && of1) || ((op == 1) && of2);
    legal = legal && !bad;

    if (op == 2) {                       // mod: slot b1 := copy of slot b2
      if (lane == b1) myptr = pa;
      unsigned a1 = (f1 >> b2) & 1u, a2 = (f2 >> b2) & 1u;
      f1 = (f1 & ~(1u << b1)) | (a1 << b1);
      f2 = (f2 & ~(1u << b1)) | (a2 << b1);
    } else if (op == 0) {
      f1 |= 1u << b1;
    } else {
      f2 |= 1u << b1;
    }
  }

  if (lane == 0) {
    g_score[k] = score;
    g_legal[k] = legal ? 1 : 0;
  }

  // ---- cold epilogue: last block reduces ----
  __threadfence();
  __syncthreads();
  __shared__ int is_last;
  if (tid == 0) is_last = (atomicAdd(&g_blocks_done, 1) == NBLK - 1) ? 1 : 0;
  __syncthreads();
  if (!is_last) return;
  __threadfence();

  float m = -INFINITY; int c = 0;
  for (int q = tid; q < KSAMP; q += 256) {
    if (g_legal[q]) { m = fmaxf(m, g_score[q]); c++; }
  }
  sred[tid] = m; scnt[tid] = c; __syncthreads();
  for (int s = 128; s > 0; s >>= 1) {
    if (tid < s) { sred[tid] = fmaxf(sred[tid], sred[tid + s]); scnt[tid] += scnt[tid + s]; }
    __syncthreads();
  }
  float gm = sred[0]; int cnt = scnt[0]; __syncthreads();

  float sum = 0.0f;
  for (int q = tid; q < KSAMP; q += 256) {
    if (g_legal[q]) sum += expf(g_score[q] - gm);
  }
  sred[tid] = sum; __syncthreads();
  for (int s = 128; s > 0; s >>= 1) {
    if (tid < s) sred[tid] += sred[tid + s];
    __syncthreads();
  }

  if (tid == 0) {
    float lse = gm + logf(sred[0]);
    double log_all = lgamma(21.0) + log(1767263190.0) + 19.0 * log(3.0);
    double res = log_all + (double)logf((float)cnt) - 2.0 * log(4096.0) + (double)lse;
    out[0] = (float)res;
    g_blocks_done = 0;                   // reset for next graph replay
    g_prep_done = 0;
  }
}

// ---------------- Launch ------------------------------------------------------
extern "C" void kernel_launch(void* const* d_in, const int* in_sizes, int n_in,
                              void* d_out, int out_size) {
  const int*   ids = (const int*)d_in[0];
  const float* emb = (const float*)d_in[1];
  const float* lv  = (const float*)d_in[2];
  const float* fx  = (const float*)d_in[3];
  const float* Wf  = (const float*)d_in[4];
  const float* Wa  = (const float*)d_in[5];
  const float* bop = (const float*)d_in[6];
  float* out = (float*)d_out;

  // jax.random.key(42) -> (0,42); partitionable foldlike split
  uint32_t kop0, kop1, kg0, kg1;
  tf_block(0u, 42u, 0u, 0u, &kop0, &kop1);
  tf_block(0u, 42u, 0u, 1u, &kg0, &kg1);

  fused_all<<<NBLK, 256>>>(kop0, kop1, kg0, kg1,
                           ids, emb, lv, fx, Wf, Wa, bop, out);
}

// round 7
// speedup vs baseline: 1.2926x; 1.2926x over previous
#include <cuda_runtime.h>
#include <math.h>
#include <stdint.h>

#define NTOK   20
#define DVEC   256
#define KSAMP  4096
#define NSTEP  19
#define WPB    8                 /* warps (samples) per block in scan */
#define NBLK   (KSAMP/WPB)       /* 512 scan blocks */
#define ROWN   (KSAMP*NTOK)      /* 81920 keys per step */

__device__ float          g_S[NTOK*6];       // [i][0..2]=x.Wf+b, [3..5]=x.Wa
__device__ uint32_t       g_key[NSTEP*ROWN]; // packed sort keys
__device__ float          g_score[KSAMP];
__device__ unsigned char  g_legal[KSAMP];
__device__ int            g_blocks_done = 0; // reset by last scan block

// ---------------- Threefry-2x32 (20 rounds), identical to JAX ----------------
__host__ __device__ __forceinline__ void tf_block(uint32_t k0, uint32_t k1,
                                                  uint32_t x0, uint32_t x1,
                                                  uint32_t* o0, uint32_t* o1) {
  uint32_t ks2 = k0 ^ k1 ^ 0x1BD11BDAu;
  x0 += k0; x1 += k1;
#define TF_ROT(r) { x0 += x1; x1 = (x1 << (r)) | (x1 >> (32 - (r))); x1 ^= x0; }
  TF_ROT(13) TF_ROT(15) TF_ROT(26) TF_ROT(6)
  x0 += k1;  x1 += ks2 + 1u;
  TF_ROT(17) TF_ROT(29) TF_ROT(16) TF_ROT(24)
  x0 += ks2; x1 += k0 + 2u;
  TF_ROT(13) TF_ROT(15) TF_ROT(26) TF_ROT(6)
  x0 += k0;  x1 += k1 + 3u;
  TF_ROT(17) TF_ROT(29) TF_ROT(16) TF_ROT(24)
  x0 += k1;  x1 += ks2 + 4u;
  TF_ROT(13) TF_ROT(15) TF_ROT(26) TF_ROT(6)
  x0 += ks2; x1 += k0 + 5u;
#undef TF_ROT
  *o0 = x0; *o1 = x1;
}

__device__ __forceinline__ uint32_t tf_bits32(uint32_t k0, uint32_t k1, uint32_t i) {
  uint32_t a, b;
  tf_block(k0, k1, 0u, i, &a, &b);
  return a ^ b;
}

// ---------------- warp-per-token prep (lane owns 8 dims, shuffle-only) --------
__device__ __forceinline__ void prep_token(int i, int lane,
                                           const int* __restrict__ ids,
                                           const float* __restrict__ emb,
                                           const float* __restrict__ lv,
                                           const float* __restrict__ fx,
                                           const float* __restrict__ Wf,
                                           const float* __restrict__ Wa,
                                           const float* __restrict__ bop) {
  const unsigned FULL = 0xFFFFFFFFu;
  int id = ids[i];
  const float4* er = (const float4*)(emb + (size_t)id * DVEC);
  const float4* fr = (const float4*)(fx  + (size_t)id * DVEC);
  float4 e0 = er[lane * 2], e1 = er[lane * 2 + 1];
  float4 f0 = fr[lane * 2], f1 = fr[lane * 2 + 1];
  float lvv = lv[id];

  float ev[8] = {e0.x, e0.y, e0.z, e0.w, e1.x, e1.y, e1.z, e1.w};
  float fv[8] = {f0.x, f0.y, f0.z, f0.w, f1.x, f1.y, f1.z, f1.w};

  float m = ev[0];
#pragma unroll
  for (int j = 1; j < 8; j++) m = fmaxf(m, ev[j]);
#pragma unroll
  for (int o = 16; o; o >>= 1) m = fmaxf(m, __shfl_xor_sync(FULL, m, o));

  float ex[8]; float sm = 0.0f;
#pragma unroll
  for (int j = 0; j < 8; j++) { ex[j] = expf(ev[j] - m); sm += ex[j]; }
#pragma unroll
  for (int o = 16; o; o >>= 1) sm += __shfl_xor_sync(FULL, sm, o);

  float x[8];
#pragma unroll
  for (int j = 0; j < 8; j++) x[j] = (ex[j] / sm) * lvv + fv[j];

  float p[6] = {0, 0, 0, 0, 0, 0};
#pragma unroll
  for (int j = 0; j < 8; j++) {
    int d = lane * 8 + j;
    p[0] += x[j] * Wf[d * 3 + 0];
    p[1] += x[j] * Wf[d * 3 + 1];
    p[2] += x[j] * Wf[d * 3 + 2];
    p[3] += x[j] * Wa[d * 3 + 0];
    p[4] += x[j] * Wa[d * 3 + 1];
    p[5] += x[j] * Wa[d * 3 + 2];
  }
#pragma unroll
  for (int o = 16; o; o >>= 1) {
#pragma unroll
    for (int q = 0; q < 6; q++) p[q] += __shfl_xor_sync(FULL, p[q], o);
  }
  if (lane == 0) {
#pragma unroll
    for (int q = 0; q < 6; q++)
      g_S[i * 6 + q] = p[q] + (q < 3 ? bop[q] : 0.0f);
  }
}

// ---------------- Kernel 1: full-occupancy keygen (+prep in 3 blocks) ---------
// One packed sort-key per thread; writes are linear in thread index.
// Ordering of gumbel -log(-log(u)) == ordering of (bits>>9); tie-break packed
// as |key+1 (23b)|31-j (5b)| so REDUX.UMAX reproduces jax.lax.top_k exactly.
__global__ __launch_bounds__(256) void keygen_kernel(
    uint32_t kg0, uint32_t kg1,
    const int* __restrict__ ids, const float* __restrict__ emb,
    const float* __restrict__ lv, const float* __restrict__ fx,
    const float* __restrict__ Wf, const float* __restrict__ Wa,
    const float* __restrict__ bop) {
  int t = blockIdx.y;                       // step 0..18
  int n = blockIdx.x * 256 + threadIdx.x;   // 0..81919  (= k*20 + j)

  if (t == 0 && blockIdx.x < 3) {           // prep: 20 token-warps in blocks 0..2
    int wf = blockIdx.x * 8 + (threadIdx.x >> 5);
    if (wf < NTOK)
      prep_token(wf, threadIdx.x & 31, ids, emb, lv, fx, Wf, Wa, bop);
  }

  uint32_t idx = (uint32_t)t * (uint32_t)ROWN + (uint32_t)n;
  uint32_t key = tf_bits32(kg0, kg1, idx) >> 9;
  uint32_t j = (uint32_t)(n % 20);
  g_key[idx] = ((key + 1u) << 5) | (31u - j);
}

// ---------------- Kernel 2: warp-per-sample scan + cold reduce ----------------
__global__ __launch_bounds__(256) void scan_kernel(
    uint32_t kop0, uint32_t kop1, float* __restrict__ out) {
  __shared__ float sS[NTOK * 6];
  __shared__ float sred[256];
  __shared__ int   scnt[256];

  const unsigned FULL = 0xFFFFFFFFu;
  int tid = threadIdx.x;
  int lane = tid & 31, w = tid >> 5;
  int k = blockIdx.x * WPB + w;             // sample 0..4095

  if (tid < NTOK * 6) sS[tid] = g_S[tid];

  // ops: lane t computes step t's op; pack into two ballot words
  uint32_t opbits = tf_bits32(kop0, kop1, (uint32_t)(lane * KSAMP + k));
  int my_op = (int)(((opbits >> 16) % 3u + (opbits & 0xFFFFu) % 3u) % 3u);
  uint32_t opb0 = __ballot_sync(FULL, my_op & 1);
  uint32_t opb1 = __ballot_sync(FULL, my_op & 2);

  // lane j preloads its 19 keys (independent LDGs, MLP=19, L2-resident)
  uint32_t skey[NSTEP];
  int base = k * NTOK + lane;
#pragma unroll
  for (int t = 0; t < NSTEP; t++)
    skey[t] = (lane < NTOK) ? g_key[t * ROWN + base] : 0u;

  __syncthreads();                          // sS staged

  unsigned avail = 0xFFFFFu;
  unsigned f1 = 0u, f2 = 0u;
  int myptr = lane;                         // slot`lane`'s dvec-row ptr
  float score = 0.0f;
  bool legal = true;

#pragma unroll
  for (int t = 0; t < NSTEP; t++) {
    int op = (int)(((opb0 >> t) & 1u) | (((opb1 >> t) & 1u) << 1));

    uint32_t s = ((avail >> lane) & 1u) ? skey[t] : 0u;  // lanes>=20: skey=0

    uint32_t m1 = __reduce_max_sync(FULL, s);
    int b1 = (int)((~m1) & 31u);
    uint32_t s2 = (lane == b1) ? 0u : s;
    uint32_t m2 = __reduce_max_sync(FULL, s2);
    int b2 = (int)((~m2) & 31u);

    avail &= ~(1u << b2);

    int pf = __shfl_sync(FULL, myptr, b1);
    int pa = __shfl_sync(FULL, myptr, b2);
    score += sS[pf * 6 + op] + sS[pa * 6 + 3 + op];

    unsigned of1 = (f1 >> b1) & 1u;
    unsigned of2 = (f2 >> b1) & 1u;
    bool bad = ((op != 2) && of1) || ((op == 1) && of2);
    legal = legal && !bad;

    if (op == 2) {                          // mod: slot b1 := copy of slot b2
      if (lane == b1) myptr = pa;
      unsigned a1 = (f1 >> b2) & 1u, a2 = (f2 >> b2) & 1u;
      f1 = (f1 & ~(1u << b1)) | (a1 << b1);
      f2 = (f2 & ~(1u << b1)) | (a2 << b1);
    } else if (op == 0) {
      f1 |= 1u << b1;
    } else {
      f2 |= 1u << b1;
    }
  }

  if (lane == 0) {
    g_score[k] = score;
    g_legal[k] = legal ? 1 : 0;
  }

  // ---- cold epilogue: last block reduces ----
  __threadfence();
  __syncthreads();
  __shared__ int is_last;
  if (tid == 0) is_last = (atomicAdd(&g_blocks_done, 1) == NBLK - 1) ? 1 : 0;
  __syncthreads();
  if (!is_last) return;
  __threadfence();

  float m = -INFINITY; int c = 0;
  for (int q = tid; q < KSAMP; q += 256) {
    if (g_legal[q]) { m = fmaxf(m, g_score[q]); c++; }
  }
  sred[tid] = m; scnt[tid] = c; __syncthreads();
  for (int s = 128; s > 0; s >>= 1) {
    if (tid < s) { sred[tid] = fmaxf(sred[tid], sred[tid + s]); scnt[tid] += scnt[tid + s]; }
    __syncthreads();
  }
  float gm = sred[0]; int cnt = scnt[0]; __syncthreads();

  float sum = 0.0f;
  for (int q = tid; q < KSAMP; q += 256) {
    if (g_legal[q]) sum += expf(g_score[q] - gm);
  }
  sred[tid] = sum; __syncthreads();
  for (int s = 128; s > 0; s >>= 1) {
    if (tid < s) sred[tid] += sred[tid + s];
    __syncthreads();
  }

  if (tid == 0) {
    float lse = gm + logf(sred[0]);
    double log_all = lgamma(21.0) + log(1767263190.0) + 19.0 * log(3.0);
    double res = log_all + (double)logf((float)cnt) - 2.0 * log(4096.0) + (double)lse;
    out[0] = (float)res;
    g_blocks_done = 0;                      // reset for next graph replay
  }
}

// ---------------- Launch ------------------------------------------------------
extern "C" void kernel_launch(void* const* d_in, const int* in_sizes, int n_in,
                              void* d_out, int out_size) {
  const int*   ids = (const int*)d_in[0];
  const float* emb = (const float*)d_in[1];
  const float* lv  = (const float*)d_in[2];
  const float* fx  = (const float*)d_in[3];
  const float* Wf  = (const float*)d_in[4];
  const float* Wa  = (const float*)d_in[5];
  const float* bop = (const float*)d_in[6];
  float* out = (float*)d_out;

  // jax.random.key(42) -> (0,42); partitionable foldlike split
  uint32_t kop0, kop1, kg0, kg1;
  tf_block(0u, 42u, 0u, 0u, &kop0, &kop1);
  tf_block(0u, 42u, 0u, 1u, &kg0, &kg1);

  keygen_kernel<<<dim3(ROWN / 256, NSTEP), 256>>>(kg0, kg1,
                                                  ids, emb, lv, fx, Wf, Wa, bop);
  scan_kernel<<<NBLK, 256>>>(kop0, kop1, out);
}